// round 4
// baseline (speedup 1.0000x reference)
#include <cuda_runtime.h>
#include <math.h>

// ---------------------------------------------------------------------------
// HyperKA 2-layer hyperbolic GCN.  N<=131072 nodes, D=64, E edges.
// Scratch in __device__ globals (no allocation allowed).
// ---------------------------------------------------------------------------

#define MAXN 131072
#define D 64

__device__ float g_h  [(size_t)MAXN * D];   // tangent-transformed features (SpMM input)
__device__ float g_agg[(size_t)MAXN * D];   // segment-sum accumulator
__device__ float g_h1 [(size_t)MAXN * D];   // layer-1 output (residual for layer 2)

#define EPS2  1e-12f          // EPS*EPS
#define PEPS  1e-5f           // PROJ_EPS
#define DEN_EPS 1e-6f

// ---- warp helpers (warp == one node, lane l owns dims l and l+32) ----------

__device__ __forceinline__ float wsum(float v) {
#pragma unroll
    for (int o = 16; o; o >>= 1) v += __shfl_xor_sync(0xffffffffu, v, o);
    return v;
}

__device__ __forceinline__ void hproj(float& a, float& b) {
    float ss = wsum(a * a + b * b);
    float n  = sqrtf(fmaxf(ss, EPS2));
    float s  = fminf((1.0f - PEPS) / n, 1.0f);
    a *= s; b *= s;
}

__device__ __forceinline__ void expmap(float& a, float& b) {
    float ss = wsum(a * a + b * b);
    float n  = sqrtf(fmaxf(ss, EPS2));
    float s  = tanhf(n) / n;
    a *= s; b *= s;
}

__device__ __forceinline__ void logmap(float& a, float& b) {
    float ss = wsum(a * a + b * b);
    float n  = sqrtf(fmaxf(ss, EPS2));
    float s  = atanhf(fminf(n, 1.0f - PEPS)) / n;
    a *= s; b *= s;
}

// x <- mobius_add(x, y)
__device__ __forceinline__ void mobius(float& xa, float& xb, float ya, float yb) {
    float x2 = wsum(xa * xa + xb * xb);
    float y2 = wsum(ya * ya + yb * yb);
    float xy = wsum(xa * ya + xb * yb);
    float c1  = 1.0f + 2.0f * xy + y2;
    float c2  = 1.0f - x2;
    float den = fmaxf(1.0f + 2.0f * xy + x2 * y2, DEN_EPS);
    float inv = 1.0f / den;
    xa = (c1 * xa + c2 * ya) * inv;
    xb = (c1 * xb + c2 * yb) * inv;
}

// o = v @ W  (W in smem, row-major 64x64); v held as (a,b) across warp
__device__ __forceinline__ void matvec(float a, float b, const float* Ws, int lane,
                                       float& o0, float& o1) {
    o0 = 0.0f; o1 = 0.0f;
#pragma unroll
    for (int k = 0; k < 32; k++) {
        float t = __shfl_sync(0xffffffffu, a, k);
        o0 = fmaf(t, Ws[k * 64 + lane],      o0);
        o1 = fmaf(t, Ws[k * 64 + lane + 32], o1);
    }
#pragma unroll
    for (int k = 0; k < 32; k++) {
        float t = __shfl_sync(0xffffffffu, b, k);
        o0 = fmaf(t, Ws[(k + 32) * 64 + lane],      o0);
        o1 = fmaf(t, Ws[(k + 32) * 64 + lane + 32], o1);
    }
}

// ---------------------------------------------------------------------------
// K1: e0 = hyp_proj(x); t = log_map(e0); g_h = t @ W1 ; zero g_agg
// ---------------------------------------------------------------------------
__global__ void k_prelude(const float* __restrict__ x, const float* __restrict__ W, int N) {
    __shared__ float Ws[64 * 64];
    for (int i = threadIdx.x; i < 64 * 64; i += blockDim.x) Ws[i] = W[i];
    __syncthreads();

    int node = (int)((blockIdx.x * blockDim.x + threadIdx.x) >> 5);
    int lane = threadIdx.x & 31;
    if (node >= N) return;
    size_t base = (size_t)node * D;

    float a = x[base + lane], b = x[base + lane + 32];
    hproj(a, b);
    logmap(a, b);

    g_agg[base + lane] = 0.0f;
    g_agg[base + lane + 32] = 0.0f;

    float o0, o1;
    matvec(a, b, Ws, lane, o0, o1);
    g_h[base + lane] = o0;
    g_h[base + lane + 32] = o1;
}

// ---------------------------------------------------------------------------
// K2: edge scatter.  16 threads per edge, one float4 each.
// g_agg[row] += val * g_h[col]
// ---------------------------------------------------------------------------
__global__ void k_edges(const int* __restrict__ rows, const int* __restrict__ cols,
                        const float* __restrict__ vals, int E) {
    long long gid = (long long)blockIdx.x * blockDim.x + threadIdx.x;
    int e = (int)(gid >> 4);
    if (e >= E) return;
    int c = ((int)gid & 15) * 4;

    int   r  = __ldg(rows + e);
    int   cl = __ldg(cols + e);
    float v  = __ldg(vals + e);

    float4 h4 = *reinterpret_cast<const float4*>(g_h + (size_t)cl * D + c);
    float4 m  = make_float4(h4.x * v, h4.y * v, h4.z * v, h4.w * v);
    atomicAdd(reinterpret_cast<float4*>(g_agg + (size_t)r * D + c), m);
}

// ---------------------------------------------------------------------------
// K3: layer-1 epilogue + residual + layer-2 prelude (log_map + @W2).
// Re-zeroes g_agg for the second edge pass.
// ---------------------------------------------------------------------------
__global__ void k_epi1(const float* __restrict__ x, const float* __restrict__ bias,
                       const float* __restrict__ W2, int N) {
    __shared__ float Ws[64 * 64];
    for (int i = threadIdx.x; i < 64 * 64; i += blockDim.x) Ws[i] = W2[i];
    __syncthreads();

    int node = (int)((blockIdx.x * blockDim.x + threadIdx.x) >> 5);
    int lane = threadIdx.x & 31;
    if (node >= N) return;
    size_t base = (size_t)node * D;

    // bias in hyperbolic space: bh = hyp_proj(exp_map(b))
    float ba = bias[lane], bb = bias[lane + 32];
    expmap(ba, bb); hproj(ba, bb);

    float oa = g_agg[base + lane], ob = g_agg[base + lane + 32];
    g_agg[base + lane] = 0.0f;
    g_agg[base + lane + 32] = 0.0f;

    expmap(oa, ob); hproj(oa, ob);
    mobius(oa, ob, ba, bb); hproj(oa, ob);
    // activation: hyp_proj(exp_map(tanh(log_map(out))))
    logmap(oa, ob);
    oa = tanhf(oa); ob = tanhf(ob);
    expmap(oa, ob); hproj(oa, ob);

    // residual with e0 = hyp_proj(x)
    float ea = x[base + lane], eb = x[base + lane + 32];
    hproj(ea, eb);
    mobius(oa, ob, ea, eb); hproj(oa, ob);

    g_h1[base + lane] = oa;
    g_h1[base + lane + 32] = ob;

    // layer-2 prelude fused here
    logmap(oa, ob);
    float o0, o1;
    matvec(oa, ob, Ws, lane, o0, o1);
    g_h[base + lane] = o0;
    g_h[base + lane + 32] = o1;
}

// ---------------------------------------------------------------------------
// K4: layer-2 epilogue (no activation) + residual with g_h1 -> d_out
// ---------------------------------------------------------------------------
__global__ void k_epi2(const float* __restrict__ bias, float* __restrict__ out, int N) {
    int node = (int)((blockIdx.x * blockDim.x + threadIdx.x) >> 5);
    int lane = threadIdx.x & 31;
    if (node >= N) return;
    size_t base = (size_t)node * D;

    float ba = bias[lane], bb = bias[lane + 32];
    expmap(ba, bb); hproj(ba, bb);

    float oa = g_agg[base + lane], ob = g_agg[base + lane + 32];
    expmap(oa, ob); hproj(oa, ob);
    mobius(oa, ob, ba, bb); hproj(oa, ob);

    float ra = g_h1[base + lane], rb = g_h1[base + lane + 32];
    mobius(oa, ob, ra, rb); hproj(oa, ob);

    out[base + lane] = oa;
    out[base + lane + 32] = ob;
}

// ---------------------------------------------------------------------------
extern "C" void kernel_launch(void* const* d_in, const int* in_sizes, int n_in,
                              void* d_out, int out_size) {
    const float* x    = (const float*)d_in[0];
    const float* vals = (const float*)d_in[1];
    const float* W1   = (const float*)d_in[2];
    const float* b1   = (const float*)d_in[3];
    const float* W2   = (const float*)d_in[4];
    const float* b2   = (const float*)d_in[5];
    const int*   rows = (const int*)d_in[6];
    const int*   cols = (const int*)d_in[7];

    int N = in_sizes[0] / D;
    int E = in_sizes[1];

    int nodeBlocks = (N + 7) / 8;                       // 8 warps (nodes) per 256-thread block
    long long et   = (long long)E * 16;
    int edgeBlocks = (int)((et + 255) / 256);

    k_prelude<<<nodeBlocks, 256>>>(x, W1, N);
    k_edges  <<<edgeBlocks, 256>>>(rows, cols, vals, E);
    k_epi1   <<<nodeBlocks, 256>>>(x, b1, W2, N);
    k_edges  <<<edgeBlocks, 256>>>(rows, cols, vals, E);
    k_epi2   <<<nodeBlocks, 256>>>(b2, (float*)d_out, N);
}

// round 7
// speedup vs baseline: 1.2940x; 1.2940x over previous
#include <cuda_runtime.h>
#include <math.h>

// ---------------------------------------------------------------------------
// HyperKA 2-layer hyperbolic GCN.  N<=131072 nodes, D=64, E<=4M edges.
// Strategy: per-launch counting sort of edges by row, then atomic-free
// warp-per-row gather with the full hyperbolic epilogue fused in.
// ---------------------------------------------------------------------------

#define MAXN 131072
#define MAXE 4194304
#define D 64
#define FULLM 0xffffffffu

__device__ float g_h  [(size_t)MAXN * D];   // layer-1 SpMM input
__device__ float g_h2 [(size_t)MAXN * D];   // layer-2 SpMM input
__device__ float g_h1 [(size_t)MAXN * D];   // layer-1 output (residual)
__device__ int   g_counts[MAXN];
__device__ int   g_off   [MAXN];
__device__ int   g_cursor[MAXN];
__device__ int   g_bsum [1024];
__device__ int   g_bscan[1024];
__device__ int   g_scols[MAXE];
__device__ float g_svals[MAXE];

#define EPS2    1e-12f        // EPS*EPS
#define PEPS    1e-5f         // PROJ_EPS
#define DEN_EPS 1e-6f

// ---- warp helpers (warp == one node, lane l owns dims l and l+32) ----------

__device__ __forceinline__ float wsum(float v) {
#pragma unroll
    for (int o = 16; o; o >>= 1) v += __shfl_xor_sync(FULLM, v, o);
    return v;
}

__device__ __forceinline__ void hproj(float& a, float& b) {
    float ss = wsum(a * a + b * b);
    float n  = sqrtf(fmaxf(ss, EPS2));
    float s  = fminf((1.0f - PEPS) / n, 1.0f);
    a *= s; b *= s;
}

__device__ __forceinline__ void expmap(float& a, float& b) {
    float ss = wsum(a * a + b * b);
    float n  = sqrtf(fmaxf(ss, EPS2));
    float s  = tanhf(n) / n;
    a *= s; b *= s;
}

__device__ __forceinline__ void logmap(float& a, float& b) {
    float ss = wsum(a * a + b * b);
    float n  = sqrtf(fmaxf(ss, EPS2));
    float s  = atanhf(fminf(n, 1.0f - PEPS)) / n;
    a *= s; b *= s;
}

// x <- mobius_add(x, y)
__device__ __forceinline__ void mobius(float& xa, float& xb, float ya, float yb) {
    float x2 = wsum(xa * xa + xb * xb);
    float y2 = wsum(ya * ya + yb * yb);
    float xy = wsum(xa * ya + xb * yb);
    float c1  = 1.0f + 2.0f * xy + y2;
    float c2  = 1.0f - x2;
    float den = fmaxf(1.0f + 2.0f * xy + x2 * y2, DEN_EPS);
    float inv = 1.0f / den;
    xa = (c1 * xa + c2 * ya) * inv;
    xb = (c1 * xb + c2 * yb) * inv;
}

// o = v @ W  (W in smem, row-major 64x64)
__device__ __forceinline__ void matvec(float a, float b, const float* Ws, int lane,
                                       float& o0, float& o1) {
    o0 = 0.0f; o1 = 0.0f;
#pragma unroll
    for (int k = 0; k < 32; k++) {
        float t = __shfl_sync(FULLM, a, k);
        o0 = fmaf(t, Ws[k * 64 + lane],      o0);
        o1 = fmaf(t, Ws[k * 64 + lane + 32], o1);
    }
#pragma unroll
    for (int k = 0; k < 32; k++) {
        float t = __shfl_sync(FULLM, b, k);
        o0 = fmaf(t, Ws[(k + 32) * 64 + lane],      o0);
        o1 = fmaf(t, Ws[(k + 32) * 64 + lane + 32], o1);
    }
}

// warp-per-row gather: (a0,a1) = sum over row's edges of val * src[col]
__device__ __forceinline__ void gather_row(const float* __restrict__ src,
                                           int node, int lane,
                                           float& a0, float& a1) {
    int start = g_off[node];
    int deg   = g_counts[node];
    a0 = 0.0f; a1 = 0.0f;
    for (int j0 = 0; j0 < deg; j0 += 32) {
        int rem = deg - j0;
        int m = rem < 32 ? rem : 32;
        int c = 0; float v = 0.0f;
        if (lane < m) {
            c = g_scols[start + j0 + lane];
            v = g_svals[start + j0 + lane];
        }
        int j = 0;
        for (; j + 4 <= m; j += 4) {
            int   c0 = __shfl_sync(FULLM, c, j),     c1 = __shfl_sync(FULLM, c, j + 1);
            int   c2 = __shfl_sync(FULLM, c, j + 2), c3 = __shfl_sync(FULLM, c, j + 3);
            float v0 = __shfl_sync(FULLM, v, j),     v1 = __shfl_sync(FULLM, v, j + 1);
            float v2 = __shfl_sync(FULLM, v, j + 2), v3 = __shfl_sync(FULLM, v, j + 3);
            const float* p0 = src + (size_t)c0 * D + lane;
            const float* p1 = src + (size_t)c1 * D + lane;
            const float* p2 = src + (size_t)c2 * D + lane;
            const float* p3 = src + (size_t)c3 * D + lane;
            float h00 = p0[0], h01 = p0[32];
            float h10 = p1[0], h11 = p1[32];
            float h20 = p2[0], h21 = p2[32];
            float h30 = p3[0], h31 = p3[32];
            a0 = fmaf(v0, h00, a0); a1 = fmaf(v0, h01, a1);
            a0 = fmaf(v1, h10, a0); a1 = fmaf(v1, h11, a1);
            a0 = fmaf(v2, h20, a0); a1 = fmaf(v2, h21, a1);
            a0 = fmaf(v3, h30, a0); a1 = fmaf(v3, h31, a1);
        }
        for (; j < m; j++) {
            int   cc = __shfl_sync(FULLM, c, j);
            float vv = __shfl_sync(FULLM, v, j);
            const float* p = src + (size_t)cc * D + lane;
            a0 = fmaf(vv, p[0],  a0);
            a1 = fmaf(vv, p[32], a1);
        }
    }
}

// ---------------------------------------------------------------------------
// K1: g_h = log_map(hyp_proj(x)) @ W1 ; zero g_counts
// ---------------------------------------------------------------------------
__global__ void k_prelude(const float* __restrict__ x, const float* __restrict__ W, int N) {
    __shared__ float Ws[64 * 64];
    for (int i = threadIdx.x; i < 64 * 64; i += blockDim.x) Ws[i] = W[i];
    __syncthreads();

    int node = (int)((blockIdx.x * blockDim.x + threadIdx.x) >> 5);
    int lane = threadIdx.x & 31;
    if (node >= N) return;
    size_t base = (size_t)node * D;

    if (lane == 0) g_counts[node] = 0;

    float a = x[base + lane], b = x[base + lane + 32];
    hproj(a, b);
    logmap(a, b);

    float o0, o1;
    matvec(a, b, Ws, lane, o0, o1);
    g_h[base + lane] = o0;
    g_h[base + lane + 32] = o1;
}

// ---------------------------------------------------------------------------
// counting sort of edges by row
// ---------------------------------------------------------------------------
__global__ void k_hist(const int* __restrict__ rows, int E) {
    int e = blockIdx.x * blockDim.x + threadIdx.x;
    if (e >= E) return;
    atomicAdd(&g_counts[rows[e]], 1);
}

__global__ void k_scan_block(int N) {
    __shared__ int ws[32];
    int tid = threadIdx.x, lane = tid & 31, wid = tid >> 5;
    int i = blockIdx.x * 1024 + tid;
    int v = (i < N) ? g_counts[i] : 0;
    int x = v;
#pragma unroll
    for (int o = 1; o < 32; o <<= 1) {
        int t = __shfl_up_sync(FULLM, x, o);
        if (lane >= o) x += t;
    }
    if (lane == 31) ws[wid] = x;
    __syncthreads();
    if (wid == 0) {
        int y = ws[lane];
#pragma unroll
        for (int o = 1; o < 32; o <<= 1) {
            int t = __shfl_up_sync(FULLM, y, o);
            if (lane >= o) y += t;
        }
        ws[lane] = y;
    }
    __syncthreads();
    int wpre = (wid == 0) ? 0 : ws[wid - 1];
    if (i < N) g_off[i] = wpre + x - v;          // exclusive within block
    if (tid == 1023) g_bsum[blockIdx.x] = wpre + x;  // block total
}

__global__ void k_scan_top(int nb) {
    __shared__ int ws[32];
    int tid = threadIdx.x, lane = tid & 31, wid = tid >> 5;
    int v = (tid < nb) ? g_bsum[tid] : 0;
    int x = v;
#pragma unroll
    for (int o = 1; o < 32; o <<= 1) {
        int t = __shfl_up_sync(FULLM, x, o);
        if (lane >= o) x += t;
    }
    if (lane == 31) ws[wid] = x;
    __syncthreads();
    if (wid == 0) {
        int y = ws[lane];
#pragma unroll
        for (int o = 1; o < 32; o <<= 1) {
            int t = __shfl_up_sync(FULLM, y, o);
            if (lane >= o) y += t;
        }
        ws[lane] = y;
    }
    __syncthreads();
    int wpre = (wid == 0) ? 0 : ws[wid - 1];
    if (tid < nb) g_bscan[tid] = wpre + x - v;   // exclusive scan of block sums
}

__global__ void k_scan_add(int N) {
    int i = blockIdx.x * blockDim.x + threadIdx.x;
    if (i >= N) return;
    int o = g_off[i] + g_bscan[i >> 10];
    g_off[i] = o;
    g_cursor[i] = o;
}

__global__ void k_reorder(const int* __restrict__ rows, const int* __restrict__ cols,
                          const float* __restrict__ vals, int E) {
    int e = blockIdx.x * blockDim.x + threadIdx.x;
    if (e >= E) return;
    int r = rows[e];
    int p = atomicAdd(&g_cursor[r], 1);
    g_scols[p] = cols[e];
    g_svals[p] = vals[e];
}

// ---------------------------------------------------------------------------
// K-layer1: gather(g_h) -> epilogue+act -> residual(e0) -> g_h1,
//           then log_map + @W2 -> g_h2
// ---------------------------------------------------------------------------
__global__ void k_layer1(const float* __restrict__ x, const float* __restrict__ bias,
                         const float* __restrict__ W2, int N) {
    __shared__ float Ws[64 * 64];
    for (int i = threadIdx.x; i < 64 * 64; i += blockDim.x) Ws[i] = W2[i];
    __syncthreads();

    int node = (int)((blockIdx.x * blockDim.x + threadIdx.x) >> 5);
    int lane = threadIdx.x & 31;
    if (node >= N) return;
    size_t base = (size_t)node * D;

    float oa, ob;
    gather_row(g_h, node, lane, oa, ob);

    // bias in hyperbolic space
    float ba = bias[lane], bb = bias[lane + 32];
    expmap(ba, bb); hproj(ba, bb);

    expmap(oa, ob); hproj(oa, ob);
    mobius(oa, ob, ba, bb); hproj(oa, ob);
    // activation: hyp_proj(exp_map(tanh(log_map(out))))
    logmap(oa, ob);
    oa = tanhf(oa); ob = tanhf(ob);
    expmap(oa, ob); hproj(oa, ob);

    // residual with e0 = hyp_proj(x)
    float ea = x[base + lane], eb = x[base + lane + 32];
    hproj(ea, eb);
    mobius(oa, ob, ea, eb); hproj(oa, ob);

    g_h1[base + lane] = oa;
    g_h1[base + lane + 32] = ob;

    // layer-2 prelude
    logmap(oa, ob);
    float o0, o1;
    matvec(oa, ob, Ws, lane, o0, o1);
    g_h2[base + lane] = o0;
    g_h2[base + lane + 32] = o1;
}

// ---------------------------------------------------------------------------
// K-layer2: gather(g_h2) -> epilogue (no act) -> residual(g_h1) -> out
// ---------------------------------------------------------------------------
__global__ void k_layer2(const float* __restrict__ bias, float* __restrict__ out, int N) {
    int node = (int)((blockIdx.x * blockDim.x + threadIdx.x) >> 5);
    int lane = threadIdx.x & 31;
    if (node >= N) return;
    size_t base = (size_t)node * D;

    float oa, ob;
    gather_row(g_h2, node, lane, oa, ob);

    float ba = bias[lane], bb = bias[lane + 32];
    expmap(ba, bb); hproj(ba, bb);

    expmap(oa, ob); hproj(oa, ob);
    mobius(oa, ob, ba, bb); hproj(oa, ob);

    float ra = g_h1[base + lane], rb = g_h1[base + lane + 32];
    mobius(oa, ob, ra, rb); hproj(oa, ob);

    out[base + lane] = oa;
    out[base + lane + 32] = ob;
}

// ---------------------------------------------------------------------------
extern "C" void kernel_launch(void* const* d_in, const int* in_sizes, int n_in,
                              void* d_out, int out_size) {
    const float* x    = (const float*)d_in[0];
    const float* vals = (const float*)d_in[1];
    const float* W1   = (const float*)d_in[2];
    const float* b1   = (const float*)d_in[3];
    const float* W2   = (const float*)d_in[4];
    const float* b2   = (const float*)d_in[5];
    const int*   rows = (const int*)d_in[6];
    const int*   cols = (const int*)d_in[7];

    int N = in_sizes[0] / D;
    int E = in_sizes[1];

    int nodeBlocks = (N + 7) / 8;          // 8 warps (nodes) per 256-thread block
    int edgeBlocks = (E + 255) / 256;
    int nb         = (N + 1023) / 1024;    // scan blocks (<= 1024)

    k_prelude   <<<nodeBlocks, 256>>>(x, W1, N);
    k_hist      <<<edgeBlocks, 256>>>(rows, E);
    k_scan_block<<<nb, 1024>>>(N);
    k_scan_top  <<<1, 1024>>>(nb);
    k_scan_add  <<<(N + 255) / 256, 256>>>(N);
    k_reorder   <<<edgeBlocks, 256>>>(rows, cols, vals, E);
    k_layer1    <<<nodeBlocks, 256>>>(x, b1, W2, N);
    k_layer2    <<<nodeBlocks, 256>>>(b2, (float*)d_out, N);
}

// round 9
// speedup vs baseline: 1.4295x; 1.1047x over previous
#include <cuda_runtime.h>
#include <cuda_fp16.h>
#include <math.h>

// ---------------------------------------------------------------------------
// HyperKA 2-layer hyperbolic GCN.  N<=131072 nodes, D=64, E<=4M edges.
// Counting-sort edges by row once per launch, then atomic-free warp-per-row
// gather.  SpMM operand rows stored as half2 (one 128B line per node) so each
// edge gather is a single coalesced wavefront.  All math in fp32.
// ---------------------------------------------------------------------------

#define MAXN 131072
#define MAXE 4194304
#define D 64
#define FULLM 0xffffffffu

__device__ __half2 g_hh [(size_t)MAXN * 32];  // layer-1 SpMM input (dim l, dim l+32)
__device__ __half2 g_hh2[(size_t)MAXN * 32];  // layer-2 SpMM input
__device__ float   g_h1 [(size_t)MAXN * D];   // layer-1 output (residual), fp32
__device__ int     g_counts[MAXN];
__device__ int     g_off   [MAXN];
__device__ int     g_cursor[MAXN];
__device__ int     g_bsum [1024];
__device__ int     g_bscan[1024];
__device__ int2    g_edge [MAXE];             // .x = col, .y = val bits

#define EPS2    1e-12f        // EPS*EPS
#define PEPS    1e-5f         // PROJ_EPS
#define DEN_EPS 1e-6f

// ---- warp helpers (warp == one node, lane l owns dims l and l+32) ----------

__device__ __forceinline__ float wsum(float v) {
#pragma unroll
    for (int o = 16; o; o >>= 1) v += __shfl_xor_sync(FULLM, v, o);
    return v;
}

__device__ __forceinline__ void hproj(float& a, float& b) {
    float ss = wsum(a * a + b * b);
    float n  = sqrtf(fmaxf(ss, EPS2));
    float s  = fminf((1.0f - PEPS) / n, 1.0f);
    a *= s; b *= s;
}

__device__ __forceinline__ void expmap(float& a, float& b) {
    float ss = wsum(a * a + b * b);
    float n  = sqrtf(fmaxf(ss, EPS2));
    float s  = tanhf(n) / n;
    a *= s; b *= s;
}

__device__ __forceinline__ void logmap(float& a, float& b) {
    float ss = wsum(a * a + b * b);
    float n  = sqrtf(fmaxf(ss, EPS2));
    float s  = atanhf(fminf(n, 1.0f - PEPS)) / n;
    a *= s; b *= s;
}

// x <- mobius_add(x, y)
__device__ __forceinline__ void mobius(float& xa, float& xb, float ya, float yb) {
    float x2 = wsum(xa * xa + xb * xb);
    float y2 = wsum(ya * ya + yb * yb);
    float xy = wsum(xa * ya + xb * yb);
    float c1  = 1.0f + 2.0f * xy + y2;
    float c2  = 1.0f - x2;
    float den = fmaxf(1.0f + 2.0f * xy + x2 * y2, DEN_EPS);
    float inv = 1.0f / den;
    xa = (c1 * xa + c2 * ya) * inv;
    xb = (c1 * xb + c2 * yb) * inv;
}

// o = v @ W  (W in smem, row-major 64x64)
__device__ __forceinline__ void matvec(float a, float b, const float* Ws, int lane,
                                       float& o0, float& o1) {
    o0 = 0.0f; o1 = 0.0f;
#pragma unroll
    for (int k = 0; k < 32; k++) {
        float t = __shfl_sync(FULLM, a, k);
        o0 = fmaf(t, Ws[k * 64 + lane],      o0);
        o1 = fmaf(t, Ws[k * 64 + lane + 32], o1);
    }
#pragma unroll
    for (int k = 0; k < 32; k++) {
        float t = __shfl_sync(FULLM, b, k);
        o0 = fmaf(t, Ws[(k + 32) * 64 + lane],      o0);
        o1 = fmaf(t, Ws[(k + 32) * 64 + lane + 32], o1);
    }
}

// warp-per-row gather: (a0,a1) = sum over row's edges of val * src[col]
// src row = 32 half2 (128B); lane l reads entry l -> one wavefront per edge.
__device__ __forceinline__ void gather_row(const __half2* __restrict__ src,
                                           int node, int lane,
                                           float& a0, float& a1) {
    int start = g_off[node];
    int deg   = g_counts[node];
    a0 = 0.0f; a1 = 0.0f;
    for (int j0 = 0; j0 < deg; j0 += 32) {
        int rem = deg - j0;
        int m = rem < 32 ? rem : 32;
        int2 ev = make_int2(0, 0);
        if (lane < m) ev = g_edge[start + j0 + lane];
        int j = 0;
        for (; j + 4 <= m; j += 4) {
            int   c0 = __shfl_sync(FULLM, ev.x, j);
            int   c1 = __shfl_sync(FULLM, ev.x, j + 1);
            int   c2 = __shfl_sync(FULLM, ev.x, j + 2);
            int   c3 = __shfl_sync(FULLM, ev.x, j + 3);
            float v0 = __int_as_float(__shfl_sync(FULLM, ev.y, j));
            float v1 = __int_as_float(__shfl_sync(FULLM, ev.y, j + 1));
            float v2 = __int_as_float(__shfl_sync(FULLM, ev.y, j + 2));
            float v3 = __int_as_float(__shfl_sync(FULLM, ev.y, j + 3));
            float2 f0 = __half22float2(src[(size_t)c0 * 32 + lane]);
            float2 f1 = __half22float2(src[(size_t)c1 * 32 + lane]);
            float2 f2 = __half22float2(src[(size_t)c2 * 32 + lane]);
            float2 f3 = __half22float2(src[(size_t)c3 * 32 + lane]);
            a0 = fmaf(v0, f0.x, a0); a1 = fmaf(v0, f0.y, a1);
            a0 = fmaf(v1, f1.x, a0); a1 = fmaf(v1, f1.y, a1);
            a0 = fmaf(v2, f2.x, a0); a1 = fmaf(v2, f2.y, a1);
            a0 = fmaf(v3, f3.x, a0); a1 = fmaf(v3, f3.y, a1);
        }
        for (; j < m; j++) {
            int   cc = __shfl_sync(FULLM, ev.x, j);
            float vv = __int_as_float(__shfl_sync(FULLM, ev.y, j));
            float2 f = __half22float2(src[(size_t)cc * 32 + lane]);
            a0 = fmaf(vv, f.x, a0);
            a1 = fmaf(vv, f.y, a1);
        }
    }
}

// ---------------------------------------------------------------------------
// K1: g_hh = half2( log_map(hyp_proj(x)) @ W1 ) ; zero g_counts
// ---------------------------------------------------------------------------
__global__ void k_prelude(const float* __restrict__ x, const float* __restrict__ W, int N) {
    __shared__ float Ws[64 * 64];
    for (int i = threadIdx.x; i < 64 * 64; i += blockDim.x) Ws[i] = W[i];
    __syncthreads();

    int node = (int)((blockIdx.x * blockDim.x + threadIdx.x) >> 5);
    int lane = threadIdx.x & 31;
    if (node >= N) return;
    size_t base = (size_t)node * D;

    if (lane == 0) g_counts[node] = 0;

    float a = x[base + lane], b = x[base + lane + 32];
    hproj(a, b);
    logmap(a, b);

    float o0, o1;
    matvec(a, b, Ws, lane, o0, o1);
    g_hh[(size_t)node * 32 + lane] = __floats2half2_rn(o0, o1);
}

// ---------------------------------------------------------------------------
// counting sort of edges by row
// ---------------------------------------------------------------------------
__global__ void k_hist(const int* __restrict__ rows, int E) {
    int e = blockIdx.x * blockDim.x + threadIdx.x;
    if (e >= E) return;
    atomicAdd(&g_counts[rows[e]], 1);
}

__global__ void k_scan_block(int N) {
    __shared__ int ws[32];
    int tid = threadIdx.x, lane = tid & 31, wid = tid >> 5;
    int i = blockIdx.x * 1024 + tid;
    int v = (i < N) ? g_counts[i] : 0;
    int x = v;
#pragma unroll
    for (int o = 1; o < 32; o <<= 1) {
        int t = __shfl_up_sync(FULLM, x, o);
        if (lane >= o) x += t;
    }
    if (lane == 31) ws[wid] = x;
    __syncthreads();
    if (wid == 0) {
        int y = ws[lane];
#pragma unroll
        for (int o = 1; o < 32; o <<= 1) {
            int t = __shfl_up_sync(FULLM, y, o);
            if (lane >= o) y += t;
        }
        ws[lane] = y;
    }
    __syncthreads();
    int wpre = (wid == 0) ? 0 : ws[wid - 1];
    if (i < N) g_off[i] = wpre + x - v;               // exclusive within block
    if (tid == 1023) g_bsum[blockIdx.x] = wpre + x;   // block total
}

__global__ void k_scan_top(int nb) {
    __shared__ int ws[32];
    int tid = threadIdx.x, lane = tid & 31, wid = tid >> 5;
    int v = (tid < nb) ? g_bsum[tid] : 0;
    int x = v;
#pragma unroll
    for (int o = 1; o < 32; o <<= 1) {
        int t = __shfl_up_sync(FULLM, x, o);
        if (lane >= o) x += t;
    }
    if (lane == 31) ws[wid] = x;
    __syncthreads();
    if (wid == 0) {
        int y = ws[lane];
#pragma unroll
        for (int o = 1; o < 32; o <<= 1) {
            int t = __shfl_up_sync(FULLM, y, o);
            if (lane >= o) y += t;
        }
        ws[lane] = y;
    }
    __syncthreads();
    int wpre = (wid == 0) ? 0 : ws[wid - 1];
    if (tid < nb) g_bscan[tid] = wpre + x - v;        // exclusive scan of block sums
}

__global__ void k_scan_add(int N) {
    int i = blockIdx.x * blockDim.x + threadIdx.x;
    if (i >= N) return;
    int o = g_off[i] + g_bscan[i >> 10];
    g_off[i] = o;
    g_cursor[i] = o;
}

__global__ void k_reorder(const int* __restrict__ rows, const int* __restrict__ cols,
                          const float* __restrict__ vals, int E) {
    int e = blockIdx.x * blockDim.x + threadIdx.x;
    if (e >= E) return;
    int r = rows[e];
    int p = atomicAdd(&g_cursor[r], 1);
    g_edge[p] = make_int2(cols[e], __float_as_int(vals[e]));
}

// ---------------------------------------------------------------------------
// K-layer1: gather(g_hh) -> epilogue+act -> residual(e0) -> g_h1,
//           then log_map + @W2 -> g_hh2
// ---------------------------------------------------------------------------
__global__ void k_layer1(const float* __restrict__ x, const float* __restrict__ bias,
                         const float* __restrict__ W2, int N) {
    __shared__ float Ws[64 * 64];
    for (int i = threadIdx.x; i < 64 * 64; i += blockDim.x) Ws[i] = W2[i];
    __syncthreads();

    int node = (int)((blockIdx.x * blockDim.x + threadIdx.x) >> 5);
    int lane = threadIdx.x & 31;
    if (node >= N) return;
    size_t base = (size_t)node * D;

    float oa, ob;
    gather_row(g_hh, node, lane, oa, ob);

    // bias in hyperbolic space
    float ba = bias[lane], bb = bias[lane + 32];
    expmap(ba, bb); hproj(ba, bb);

    expmap(oa, ob); hproj(oa, ob);
    mobius(oa, ob, ba, bb); hproj(oa, ob);
    // activation: hyp_proj(exp_map(tanh(log_map(out))))
    logmap(oa, ob);
    oa = tanhf(oa); ob = tanhf(ob);
    expmap(oa, ob); hproj(oa, ob);

    // residual with e0 = hyp_proj(x)
    float ea = x[base + lane], eb = x[base + lane + 32];
    hproj(ea, eb);
    mobius(oa, ob, ea, eb); hproj(oa, ob);

    g_h1[base + lane] = oa;
    g_h1[base + lane + 32] = ob;

    // layer-2 prelude
    logmap(oa, ob);
    float o0, o1;
    matvec(oa, ob, Ws, lane, o0, o1);
    g_hh2[(size_t)node * 32 + lane] = __floats2half2_rn(o0, o1);
}

// ---------------------------------------------------------------------------
// K-layer2: gather(g_hh2) -> epilogue (no act) -> residual(g_h1) -> out
// ---------------------------------------------------------------------------
__global__ void k_layer2(const float* __restrict__ bias, float* __restrict__ out, int N) {
    int node = (int)((blockIdx.x * blockDim.x + threadIdx.x) >> 5);
    int lane = threadIdx.x & 31;
    if (node >= N) return;
    size_t base = (size_t)node * D;

    float oa, ob;
    gather_row(g_hh2, node, lane, oa, ob);

    float ba = bias[lane], bb = bias[lane + 32];
    expmap(ba, bb); hproj(ba, bb);

    expmap(oa, ob); hproj(oa, ob);
    mobius(oa, ob, ba, bb); hproj(oa, ob);

    float ra = g_h1[base + lane], rb = g_h1[base + lane + 32];
    mobius(oa, ob, ra, rb); hproj(oa, ob);

    out[base + lane] = oa;
    out[base + lane + 32] = ob;
}

// ---------------------------------------------------------------------------
extern "C" void kernel_launch(void* const* d_in, const int* in_sizes, int n_in,
                              void* d_out, int out_size) {
    const float* x    = (const float*)d_in[0];
    const float* vals = (const float*)d_in[1];
    const float* W1   = (const float*)d_in[2];
    const float* b1   = (const float*)d_in[3];
    const float* W2   = (const float*)d_in[4];
    const float* b2   = (const float*)d_in[5];
    const int*   rows = (const int*)d_in[6];
    const int*   cols = (const int*)d_in[7];

    int N = in_sizes[0] / D;
    int E = in_sizes[1];

    int nodeBlocks = (N + 7) / 8;          // 8 warps (nodes) per 256-thread block
    int edgeBlocks = (E + 255) / 256;
    int nb         = (N + 1023) / 1024;    // scan blocks (<= 1024)

    k_prelude   <<<nodeBlocks, 256>>>(x, W1, N);
    k_hist      <<<edgeBlocks, 256>>>(rows, E);
    k_scan_block<<<nb, 1024>>>(N);
    k_scan_top  <<<1, 1024>>>(nb);
    k_scan_add  <<<(N + 255) / 256, 256>>>(N);
    k_reorder   <<<edgeBlocks, 256>>>(rows, cols, vals, E);
    k_layer1    <<<nodeBlocks, 256>>>(x, b1, W2, N);
    k_layer2    <<<nodeBlocks, 256>>>(b2, (float*)d_out, N);
}